// round 6
// baseline (speedup 1.0000x reference)
#include <cuda_runtime.h>
#include <cstdint>

#define FULLMASK 0xffffffffu
using ull = unsigned long long;

constexpr int NN = 22;
constexpr int D  = 64;

// U table: rows 0-2 = w2[t][:] (= W[t] @ a[t,64:]), rows 3-11 = M1[s*3+t][:] (= W[s] @ a[t,:64])
__device__ __align__(16) float g_U[12*64];
__device__ int g_mflag;   // 1 => mask buffer is uint8, 0 => int32

__device__ __forceinline__ ull fma2(ull a, ull b, ull c) {
    ull d; asm("fma.rn.f32x2 %0, %1, %2, %3;" : "=l"(d) : "l"(a), "l"(b), "l"(c)); return d;
}
__device__ __forceinline__ ull pack2(float v) {
    ull r; asm("mov.b64 %0, {%1, %1};" : "=l"(r) : "f"(v)); return r;
}
__device__ __forceinline__ float lo32(ull v){ return __uint_as_float((unsigned)v); }
__device__ __forceinline__ float hi32(ull v){ return __uint_as_float((unsigned)(v >> 32)); }

__device__ __forceinline__ float dot64(const float* __restrict__ x, const float* __restrict__ y) {
    const float4* xp = (const float4*)x;
    const float4* yp = (const float4*)y;
    float a0 = 0.f, a1 = 0.f, a2 = 0.f, a3 = 0.f;
    #pragma unroll
    for (int k = 0; k < 16; ++k) {
        float4 u = __ldg(xp + k), v = __ldg(yp + k);
        a0 = fmaf(u.x, v.x, a0); a1 = fmaf(u.y, v.y, a1);
        a2 = fmaf(u.z, v.z, a2); a3 = fmaf(u.w, v.w, a3);
    }
    return (a0 + a1) + (a2 + a3);
}

// ================= prep: 6 blocks x 128, one thread per U entry =================
__global__ __launch_bounds__(128) void hetgat_prep(
    const float* __restrict__ W, const float* __restrict__ a,
    const void* __restrict__ maskp)
{
    const int tid = threadIdx.x;
    const int idx = blockIdx.x * 128 + tid;

    if (blockIdx.x == 0 && tid < 32) {
        const int* mi = (const int*)maskp;
        unsigned v0 = (unsigned)__ldg(mi + tid);
        unsigned v1 = (unsigned)__ldg(mi + 32 + tid);
        int bad = __any_sync(FULLMASK, (v0 > 1u) || (v1 > 1u));
        if (tid == 0) g_mflag = bad;
    }

    if (idx < 768) {
        const float* row; const float* av; float* dst;
        if (idx < 192) {                 // w2 rows
            int t = idx >> 6, d = idx & 63;
            row = W + (t*D + d)*D;  av = a + t*128 + 64;  dst = g_U + t*64 + d;
        } else {                         // M1 rows
            int r = idx - 192; int v = r >> 6, d = r & 63; int s = v/3, t = v - s*3;
            row = W + (s*D + d)*D;  av = a + t*128;        dst = g_U + (3 + v)*64 + d;
        }
        *dst = dot64(row, av);
    }
}

// ================= main: 128 threads, 1 batch/warp, (B+3)/4 blocks =================
__global__ __launch_bounds__(128, 7) void hetgat_main(
    const float* __restrict__ h,      // (B, 22, 64)
    const void*  __restrict__ maskp,  // (3, B, 22)
    const float* __restrict__ W,      // (3, 64, 64): row k=t*64+d, h contiguous
    float* __restrict__ out,          // (B, 64)
    int B)
{
    __shared__ __align__(16) float s_c[4][96];        // per-warp coeffs c[t*32+node]
    __shared__ __align__(16) float s_g[4][200];       // per-batch g[k], pitch 200 (bank spread)
    __shared__ __align__(16) float s_part[4][4][64];  // [kwarp][batch][hcol] partials

    const int tid  = threadIdx.x;
    const int wid  = tid >> 5;
    const int lane = tid & 31;

    const bool u8m = (__ldg(&g_mflag) != 0);
    const int* mi32 = (const int*)maskp;
    const uint8_t* mu8 = (const uint8_t*)maskp;
    const size_t mT = (size_t)B * NN;

    const int b = blockIdx.x * 4 + wid;   // one batch per warp
    const int bbase = blockIdx.x * 4;

    // per-lane pair mapping
    const int  tA = lane / 10;                  // 3 for lanes 30,31
    const int  nA = 1 + (lane - tA*10);
    const bool validA = (lane < 30);
    const int  tAe = validA ? tA : 2;           // lanes 30,31 compute extra pair (2,21)
    const int  nAe = validA ? nA : 21;
    const int  tO = lane / 11;                  // all 32 lanes valid (lane31 dup of (2,20))
    const int  nO = 11 + (lane - tO*11);

    if (b < B) {
        const size_t boff = (size_t)b * NN;
        auto mld = [&](int t, int node) -> int {
            size_t i = (size_t)t * mT + boff + node;
            return u8m ? (int)mu8[i] : mi32[i];
        };
        // mask prefetch
        int mAv = 1, mOv, mEv = 1, mSv = 0;
        if (validA)     mAv = mld(tA, nA);
        mOv = mld(tO, nO);
        if (lane == 30) mEv = mld(2, 21);
        if (lane < 3)   mSv = mld(lane, 0);

        const float* hb = h + (size_t)b * (NN*D);

        // ---- pair-per-lane dots (no shuffles) ----
        const float dA = dot64(hb + nAe*D, g_U + tAe*64);        // ally (lane30/31: extra opp pair)
        const float dO = dot64(hb + nO*D,  g_U + tO*64);         // opp
        const int   vs = (lane < 9) ? lane : 0;
        const float dS = dot64(hb, g_U + (3 + vs)*64);           // self st[s*3+t] in lanes 0-8

        // ---- softmax (no max-subtraction; logits ~N(0,1), shift-invariant) ----
        float s0A = __shfl_sync(FULLMASK, dS, tAe);
        float s1A = __shfl_sync(FULLMASK, dS, 3 + tAe);
        float s2A = __shfl_sync(FULLMASK, dS, 6 + tAe);
        float s0O = __shfl_sync(FULLMASK, dS, tO);
        float s1O = __shfl_sync(FULLMASK, dS, 3 + tO);
        float s2O = __shfl_sync(FULLMASK, dS, 6 + tO);

        float lsA = 0.f;
        if (validA && mAv == 0)
            lsA = __expf(s0A + dA) + __expf(s1A + dA) + __expf(s2A + dA);
        float lsO = 0.f;
        if (mOv == 0)
            lsO = __expf(s0O + dO) + __expf(s1O + dO) + __expf(s2O + dO);
        float lsE = 0.f;
        if (lane == 30 && mEv == 0)      // extra opp pair (t=2, node 21); uses dA slot
            lsE = __expf(s0O + dA) + __expf(s1O + dA) + __expf(s2O + dA);

        float SA = lsA, SO = lsO + lsE;
        #pragma unroll
        for (int off = 16; off > 0; off >>= 1) {
            SA += __shfl_xor_sync(FULLMASK, SA, off);
            SO += __shfl_xor_sync(FULLMASK, SO, off);
        }

        if (validA)     s_c[wid][tA*32 + nA]  = (mAv == 0) ? __fdividef(lsA, SA) : 0.f;
        s_c[wid][tO*32 + nO] = (mOv == 0) ? __fdividef(lsO, SO) : 0.f;
        if (lane == 30) s_c[wid][2*32 + 21]   = (mEv == 0) ? __fdividef(lsE, SO) : 0.f;
        if (lane < 3)   s_c[wid][lane*32 + 0] = mSv ? 1.0f : 0.0f;
        __syncwarp();

        // ---- combine: g[t][d] = sum_n c[t][n]*h[n][d]; lane owns d = 2l, 2l+1 ----
        const float2* hb2 = (const float2*)hb;
        const float* sc = s_c[wid];
        float gx0=0.f, gy0=0.f, gx1=0.f, gy1=0.f, gx2=0.f, gy2=0.f;
        #pragma unroll
        for (int n = 0; n < NN; ++n) {
            float2 hv = __ldg(hb2 + n*32 + lane);    // L1 hit (loaded by dots)
            float c0 = sc[n], c1 = sc[32 + n], c2 = sc[64 + n];
            gx0 = fmaf(c0, hv.x, gx0); gy0 = fmaf(c0, hv.y, gy0);
            gx1 = fmaf(c1, hv.x, gx1); gy1 = fmaf(c1, hv.y, gy1);
            gx2 = fmaf(c2, hv.x, gx2); gy2 = fmaf(c2, hv.y, gy2);
        }
        ((float2*)(s_g[wid]      ))[lane] = make_float2(gx0, gy0);
        ((float2*)(s_g[wid] +  64))[lane] = make_float2(gx1, gy1);
        ((float2*)(s_g[wid] + 128))[lane] = make_float2(gx2, gy2);
    }
    __syncthreads();

    // ---- block-cooperative mat-vec: warp wid handles k in [48*wid, 48*wid+48) for ALL 4 batches ----
    // lane = (bt, hlg): bt = lane>>3 (batch in block), hlg = lane&7 (h cols 8*hlg..8*hlg+7)
    {
        const int bt  = lane >> 3;
        const int hlg = lane & 7;
        const int kbase = wid * 48;
        const float* gv = s_g[bt];
        ull a0 = 0ull, a1 = 0ull, a2 = 0ull, a3 = 0ull;
        #pragma unroll 8
        for (int i = 0; i < 48; ++i) {
            const int k = kbase + i;
            ull gk = pack2(gv[k]);                       // LDS broadcast (4 banks)
            const ulonglong2* wp = (const ulonglong2*)(W + k*D + hlg*8);
            ulonglong2 w01 = __ldg(wp);                  // cols 8hlg..+3 (dedup x4 lanes)
            ulonglong2 w23 = __ldg(wp + 1);              // cols +4..+7
            a0 = fma2(gk, w01.x, a0); a1 = fma2(gk, w01.y, a1);
            a2 = fma2(gk, w23.x, a2); a3 = fma2(gk, w23.y, a3);
        }
        float4 f0 = make_float4(lo32(a0), hi32(a0), lo32(a1), hi32(a1));
        float4 f1 = make_float4(lo32(a2), hi32(a2), lo32(a3), hi32(a3));
        *(float4*)&s_part[wid][bt][hlg*8]     = f0;
        *(float4*)&s_part[wid][bt][hlg*8 + 4] = f1;
    }
    __syncthreads();

    // ---- reduce partials + ELU + store: warp wid writes batch wid, lane owns cols 2l, 2l+1 ----
    if (b < B) {
        float rx = 0.f, ry = 0.f;
        #pragma unroll
        for (int w = 0; w < 4; ++w) {
            float2 v = *(const float2*)&s_part[w][wid][lane*2];
            rx += v.x; ry += v.y;
        }
        float2 o;
        o.x = (rx > 0.f) ? rx : expm1f(rx);
        o.y = (ry > 0.f) ? ry : expm1f(ry);
        ((float2*)(out + (size_t)b * D))[lane] = o;
    }
    (void)bbase;
}

extern "C" void kernel_launch(void* const* d_in, const int* in_sizes, int n_in,
                              void* d_out, int out_size)
{
    const float* h = nullptr;
    const void* mask = nullptr;
    const float* W = nullptr;
    const float* a = nullptr;
    long hsz = 0; int hidx = -1;
    for (int i = 0; i < n_in; ++i) {
        if (in_sizes[i] == 12288)      W = (const float*)d_in[i];
        else if (in_sizes[i] == 384)   a = (const float*)d_in[i];
        if ((long)in_sizes[i] > hsz) { hsz = in_sizes[i]; hidx = i; }
    }
    h = (const float*)d_in[hidx];
    const int B = (int)(hsz / (NN * D));
    for (int i = 0; i < n_in; ++i) {
        if (i != hidx && (long)in_sizes[i] == (long)3 * B * NN)
            mask = d_in[i];
    }

    hetgat_prep<<<6, 128>>>(W, a, mask);
    hetgat_main<<<(B + 3) / 4, 128>>>(h, mask, W, (float*)d_out, B);
}

// round 8
// speedup vs baseline: 1.3709x; 1.3709x over previous
#include <cuda_runtime.h>
#include <cstdint>

#define FULLMASK 0xffffffffu
using ull = unsigned long long;

constexpr int NN = 22;
constexpr int D  = 64;

// U table: rows 0-2 = w2[t][:] (= W[t] @ a[t,64:]), rows 3-11 = M1[s*3+t][:] (= W[s] @ a[t,:64])
__device__ __align__(16) float g_U[12*64];
__device__ int g_mflag;   // 1 => mask buffer is uint8, 0 => int32

__device__ __forceinline__ ull fma2(ull a, ull b, ull c) {
    ull d; asm("fma.rn.f32x2 %0, %1, %2, %3;" : "=l"(d) : "l"(a), "l"(b), "l"(c)); return d;
}
__device__ __forceinline__ ull pack2(float v) {
    ull r; asm("mov.b64 %0, {%1, %1};" : "=l"(r) : "f"(v)); return r;
}
__device__ __forceinline__ float lo32(ull v){ return __uint_as_float((unsigned)v); }
__device__ __forceinline__ float hi32(ull v){ return __uint_as_float((unsigned)(v >> 32)); }

__device__ __forceinline__ float dot64(const float* __restrict__ x, const float* __restrict__ y) {
    const float4* xp = (const float4*)x;
    const float4* yp = (const float4*)y;
    float a0 = 0.f, a1 = 0.f, a2 = 0.f, a3 = 0.f;
    #pragma unroll
    for (int k = 0; k < 16; ++k) {
        float4 u = __ldg(xp + k), v = __ldg(yp + k);
        a0 = fmaf(u.x, v.x, a0); a1 = fmaf(u.y, v.y, a1);
        a2 = fmaf(u.z, v.z, a2); a3 = fmaf(u.w, v.w, a3);
    }
    return (a0 + a1) + (a2 + a3);
}

// ================= prep: 6 blocks x 128, one thread per U entry =================
__global__ __launch_bounds__(128) void hetgat_prep(
    const float* __restrict__ W, const float* __restrict__ a,
    const void* __restrict__ maskp)
{
    const int tid = threadIdx.x;
    const int idx = blockIdx.x * 128 + tid;

    if (blockIdx.x == 0 && tid < 32) {
        const int* mi = (const int*)maskp;
        unsigned v0 = (unsigned)__ldg(mi + tid);
        unsigned v1 = (unsigned)__ldg(mi + 32 + tid);
        int bad = __any_sync(FULLMASK, (v0 > 1u) || (v1 > 1u));
        if (tid == 0) g_mflag = bad;
    }

    if (idx < 768) {
        const float* row; const float* av; float* dst;
        if (idx < 192) {                 // w2 rows
            int t = idx >> 6, d = idx & 63;
            row = W + (t*D + d)*D;  av = a + t*128 + 64;  dst = g_U + t*64 + d;
        } else {                         // M1 rows
            int r = idx - 192; int v = r >> 6, d = r & 63; int s = v/3, t = v - s*3;
            row = W + (s*D + d)*D;  av = a + t*128;        dst = g_U + (3 + v)*64 + d;
        }
        *dst = dot64(row, av);
    }
}

// ================= main: 128 threads, 1 batch/warp, B/4 blocks =================
__global__ __launch_bounds__(128, 6) void hetgat_main(
    const float* __restrict__ h,      // (B, 22, 64)
    const void*  __restrict__ maskp,  // (3, B, 22)
    const float* __restrict__ W,      // (3, 64, 64): row k=t*64+d, h contiguous
    float* __restrict__ out,          // (B, 64)
    int B)
{
    __shared__ __align__(16) float s_c[4][96];        // per-warp coeffs c[t*32+node]
    __shared__ __align__(16) float s_g[4][200];       // per-batch g[k], pitch 200
    __shared__ __align__(16) float s_part[4][4][64];  // [kwarp][batch][hcol] partials

    const int tid  = threadIdx.x;
    const int wid  = tid >> 5;
    const int lane = tid & 31;

    const bool u8m = (__ldg(&g_mflag) != 0);
    const int* mi32 = (const int*)maskp;
    const uint8_t* mu8 = (const uint8_t*)maskp;
    const size_t mT = (size_t)B * NN;

    const int b = blockIdx.x * 4 + wid;   // one batch per warp

    // per-lane pair mapping
    const int  tA = lane / 10;                  // 3 for lanes 30,31
    const int  nA = 1 + (lane - tA*10);
    const bool validA = (lane < 30);
    const int  tO = lane / 11;                  // lane oi -> opp pair (tO, nO); slot 31 = (2,20)
    const int  nO = 11 + (lane - tO*11);

    if (b < B) {
        const size_t boff = (size_t)b * NN;
        auto mld = [&](int t, int node) -> int {
            size_t i = (size_t)t * mT + boff + node;
            return u8m ? (int)mu8[i] : mi32[i];
        };
        // mask prefetch
        int mAv = 1, mOv, mEv = 1, mSv = 0;
        if (validA)     mAv = mld(tA, nA);
        mOv = mld(tO, nO);
        if (lane == 30) mEv = mld(2, 21);
        if (lane < 3)   mSv = mld(lane, 0);

        const float2* hb2 = (const float2*)(h + (size_t)b * (NN*D));

        // hoisted w2 lane slices (d = 2l, 2l+1)
        float w2x[3], w2y[3];
        #pragma unroll
        for (int t = 0; t < 3; ++t) {
            float2 v = __ldg(((const float2*)(g_U + t*64)) + lane);
            w2x[t] = v.x; w2y[t] = v.y;
        }

        // ======== PASS 1: ally dots (30) + opp pair (2,21) in slot 30 ========
        float p[32];
        #pragma unroll
        for (int n = 1; n <= 10; ++n) {
            float2 hv = __ldg(hb2 + n*32 + lane);
            p[n-1]      = fmaf(hv.y, w2y[0], hv.x * w2x[0]);
            p[10 + n-1] = fmaf(hv.y, w2y[1], hv.x * w2x[1]);
            p[20 + n-1] = fmaf(hv.y, w2y[2], hv.x * w2x[2]);
        }
        {
            float2 hv = __ldg(hb2 + 21*32 + lane);
            p[30] = fmaf(hv.y, w2y[2], hv.x * w2x[2]);
            p[31] = 0.f;
        }
        #pragma unroll
        for (int sh = 16; sh >= 1; sh >>= 1) {
            bool up = (lane & sh) != 0;
            #pragma unroll
            for (int k = 0; k < sh; ++k) {
                float send = up ? p[k] : p[k + sh];
                float recv = __shfl_xor_sync(FULLMASK, send, sh);
                float keep = up ? p[k + sh] : p[k];
                p[k] = keep + recv;
            }
        }
        const float dA = p[0];   // lane v: ally dot v (lane30: opp(2,21)); lane31: 0

        // ======== PASS 2: opp dots, slot oi = t*11+(n-11) for oi=0..31 ========
        // t=0: slots 0..10 (n=11..21); t=1: slots 11..21 (n=11..21);
        // t=2: slots 22..31 (n=11..20); pair (2,21) lives in pass-1 slot 30.
        #pragma unroll
        for (int n = 11; n <= 21; ++n) {
            float2 hv = __ldg(hb2 + n*32 + lane);
            p[n-11]      = fmaf(hv.y, w2y[0], hv.x * w2x[0]);
            p[11 + n-11] = fmaf(hv.y, w2y[1], hv.x * w2x[1]);
            if (n < 21) p[22 + n-11] = fmaf(hv.y, w2y[2], hv.x * w2x[2]);
        }
        #pragma unroll
        for (int sh = 16; sh >= 1; sh >>= 1) {
            bool up = (lane & sh) != 0;
            #pragma unroll
            for (int k = 0; k < sh; ++k) {
                float send = up ? p[k] : p[k + sh];
                float recv = __shfl_xor_sync(FULLMASK, send, sh);
                float keep = up ? p[k + sh] : p[k];
                p[k] = keep + recv;
            }
        }
        const float dO = p[0];   // lane oi: opp dot (tO, nO); lane31 = (2,20)

        // ======== PASS 3: self dots st[s*3+t] (9 in 16 slots) ========
        float q[16];
        {
            float2 h0 = __ldg(hb2 + lane);
            #pragma unroll
            for (int v = 0; v < 9; ++v) {
                float2 m = __ldg(((const float2*)(g_U + (3 + v)*64)) + lane);
                q[v] = fmaf(h0.y, m.y, h0.x * m.x);
            }
        }
        #pragma unroll
        for (int v = 9; v < 16; ++v) q[v] = 0.f;
        #pragma unroll
        for (int sh = 8; sh >= 1; sh >>= 1) {
            bool up = (lane & sh) != 0;
            #pragma unroll
            for (int k = 0; k < sh; ++k) {
                float send = up ? q[k] : q[k + sh];
                float recv = __shfl_xor_sync(FULLMASK, send, sh);
                float keep = up ? q[k + sh] : q[k];
                q[k] = keep + recv;
            }
        }
        q[0] += __shfl_xor_sync(FULLMASK, q[0], 16);
        const float dS = q[0];   // lanes 0-8 hold st[s*3+t]

        // ======== softmax (no max-subtraction; logits small, shift-invariant) ========
        const int tAe = validA ? tA : 2;   // lanes 30,31 borrow t=2 (extra-pair path)
        float s0A = __shfl_sync(FULLMASK, dS, tAe);
        float s1A = __shfl_sync(FULLMASK, dS, 3 + tAe);
        float s2A = __shfl_sync(FULLMASK, dS, 6 + tAe);
        float s0O = __shfl_sync(FULLMASK, dS, tO);
        float s1O = __shfl_sync(FULLMASK, dS, 3 + tO);
        float s2O = __shfl_sync(FULLMASK, dS, 6 + tO);

        float lsA = 0.f;
        if (validA && mAv == 0)
            lsA = __expf(s0A + dA) + __expf(s1A + dA) + __expf(s2A + dA);
        float lsO = 0.f;
        if (mOv == 0)
            lsO = __expf(s0O + dO) + __expf(s1O + dO) + __expf(s2O + dO);
        float lsE = 0.f;
        if (lane == 30 && mEv == 0)      // extra opp pair (t=2, node 21); dot is in dA slot 30
            lsE = __expf(s0O + dA) + __expf(s1O + dA) + __expf(s2O + dA);

        float SA = lsA, SO = lsO + lsE;
        #pragma unroll
        for (int off = 16; off > 0; off >>= 1) {
            SA += __shfl_xor_sync(FULLMASK, SA, off);
            SO += __shfl_xor_sync(FULLMASK, SO, off);
        }

        if (validA)     s_c[wid][tA*32 + nA]  = (mAv == 0) ? __fdividef(lsA, SA) : 0.f;
        s_c[wid][tO*32 + nO] = (mOv == 0) ? __fdividef(lsO, SO) : 0.f;
        if (lane == 30) s_c[wid][2*32 + 21]   = (mEv == 0) ? __fdividef(lsE, SO) : 0.f;
        if (lane < 3)   s_c[wid][lane*32 + 0] = mSv ? 1.0f : 0.0f;
        __syncwarp();

        // ======== combine: g[t][d] = sum_n c[t][n]*h[n][d]; lane owns d = 2l, 2l+1 ========
        const float* sc = s_c[wid];
        float gx0=0.f, gy0=0.f, gx1=0.f, gy1=0.f, gx2=0.f, gy2=0.f;
        #pragma unroll
        for (int n = 0; n < NN; ++n) {
            float2 hv = __ldg(hb2 + n*32 + lane);   // L1 hit
            float c0 = sc[n], c1 = sc[32 + n], c2 = sc[64 + n];
            gx0 = fmaf(c0, hv.x, gx0); gy0 = fmaf(c0, hv.y, gy0);
            gx1 = fmaf(c1, hv.x, gx1); gy1 = fmaf(c1, hv.y, gy1);
            gx2 = fmaf(c2, hv.x, gx2); gy2 = fmaf(c2, hv.y, gy2);
        }
        ((float2*)(s_g[wid]      ))[lane] = make_float2(gx0, gy0);
        ((float2*)(s_g[wid] +  64))[lane] = make_float2(gx1, gy1);
        ((float2*)(s_g[wid] + 128))[lane] = make_float2(gx2, gy2);
    }
    __syncthreads();

    // ---- block-cooperative mat-vec: warp wid covers k in [48*wid, 48*wid+48) for ALL 4 batches ----
    // lane = (bt, hlg): bt = lane>>3 (batch), hlg = lane&7 (h cols 8*hlg .. 8*hlg+7)
    {
        const int bt  = lane >> 3;
        const int hlg = lane & 7;
        const int kbase = wid * 48;
        const float* gv = s_g[bt];
        ull a0 = 0ull, a1 = 0ull, a2 = 0ull, a3 = 0ull;
        #pragma unroll 8
        for (int i = 0; i < 48; ++i) {
            const int k = kbase + i;
            ull gk = pack2(gv[k]);                       // LDS broadcast per bt
            const ulonglong2* wp = (const ulonglong2*)(W + k*D + hlg*8);
            ulonglong2 w01 = __ldg(wp);
            ulonglong2 w23 = __ldg(wp + 1);
            a0 = fma2(gk, w01.x, a0); a1 = fma2(gk, w01.y, a1);
            a2 = fma2(gk, w23.x, a2); a3 = fma2(gk, w23.y, a3);
        }
        float4 f0 = make_float4(lo32(a0), hi32(a0), lo32(a1), hi32(a1));
        float4 f1 = make_float4(lo32(a2), hi32(a2), lo32(a3), hi32(a3));
        *(float4*)&s_part[wid][bt][hlg*8]     = f0;
        *(float4*)&s_part[wid][bt][hlg*8 + 4] = f1;
    }
    __syncthreads();

    // ---- reduce partials + ELU + store: warp wid writes batch wid, lane owns cols 2l, 2l+1 ----
    if (b < B) {
        float rx = 0.f, ry = 0.f;
        #pragma unroll
        for (int w = 0; w < 4; ++w) {
            float2 v = *(const float2*)&s_part[w][wid][lane*2];
            rx += v.x; ry += v.y;
        }
        float2 o;
        o.x = (rx > 0.f) ? rx : expm1f(rx);
        o.y = (ry > 0.f) ? ry : expm1f(ry);
        ((float2*)(out + (size_t)b * D))[lane] = o;
    }
}

extern "C" void kernel_launch(void* const* d_in, const int* in_sizes, int n_in,
                              void* d_out, int out_size)
{
    const float* h = nullptr;
    const void* mask = nullptr;
    const float* W = nullptr;
    const float* a = nullptr;
    long hsz = 0; int hidx = -1;
    for (int i = 0; i < n_in; ++i) {
        if (in_sizes[i] == 12288)      W = (const float*)d_in[i];
        else if (in_sizes[i] == 384)   a = (const float*)d_in[i];
        if ((long)in_sizes[i] > hsz) { hsz = in_sizes[i]; hidx = i; }
    }
    h = (const float*)d_in[hidx];
    const int B = (int)(hsz / (NN * D));
    for (int i = 0; i < n_in; ++i) {
        if (i != hidx && (long)in_sizes[i] == (long)3 * B * NN)
            mask = d_in[i];
    }

    hetgat_prep<<<6, 128>>>(W, a, mask);
    hetgat_main<<<(B + 3) / 4, 128>>>(h, mask, W, (float*)d_out, B);
}

// round 9
// speedup vs baseline: 1.5506x; 1.1310x over previous
#include <cuda_runtime.h>
#include <cstdint>

#define FULLMASK 0xffffffffu
using ull = unsigned long long;

constexpr int NN = 22;
constexpr int D  = 64;

// U table: rows 0-2 = w2[t][:] (= W[t] @ a[t,64:]), rows 3-11 = M1[s*3+t][:] (= W[s] @ a[t,:64])
__device__ __align__(16) float g_U[12*64];
__device__ int g_mflag;   // 1 => mask buffer is uint8, 0 => int32

__device__ __forceinline__ ull fma2(ull a, ull b, ull c) {
    ull d; asm("fma.rn.f32x2 %0, %1, %2, %3;" : "=l"(d) : "l"(a), "l"(b), "l"(c)); return d;
}
__device__ __forceinline__ ull pack2(float v) {
    ull r; asm("mov.b64 %0, {%1, %1};" : "=l"(r) : "f"(v)); return r;
}
__device__ __forceinline__ float lo32(ull v){ return __uint_as_float((unsigned)v); }
__device__ __forceinline__ float hi32(ull v){ return __uint_as_float((unsigned)(v >> 32)); }

__device__ __forceinline__ float dot64(const float* __restrict__ x, const float* __restrict__ y) {
    const float4* xp = (const float4*)x;
    const float4* yp = (const float4*)y;
    float a0 = 0.f, a1 = 0.f, a2 = 0.f, a3 = 0.f;
    #pragma unroll
    for (int k = 0; k < 16; ++k) {
        float4 u = __ldg(xp + k), v = __ldg(yp + k);
        a0 = fmaf(u.x, v.x, a0); a1 = fmaf(u.y, v.y, a1);
        a2 = fmaf(u.z, v.z, a2); a3 = fmaf(u.w, v.w, a3);
    }
    return (a0 + a1) + (a2 + a3);
}

// ================= prep: 6 blocks x 128, one thread per U entry =================
__global__ __launch_bounds__(128) void hetgat_prep(
    const float* __restrict__ W, const float* __restrict__ a,
    const void* __restrict__ maskp)
{
    const int tid = threadIdx.x;
    const int idx = blockIdx.x * 128 + tid;

    if (blockIdx.x == 0 && tid < 32) {
        const int* mi = (const int*)maskp;
        unsigned v0 = (unsigned)__ldg(mi + tid);
        unsigned v1 = (unsigned)__ldg(mi + 32 + tid);
        int bad = __any_sync(FULLMASK, (v0 > 1u) || (v1 > 1u));
        if (tid == 0) g_mflag = bad;
    }

    if (idx < 768) {
        const float* row; const float* av; float* dst;
        if (idx < 192) {                 // w2 rows
            int t = idx >> 6, d = idx & 63;
            row = W + (t*D + d)*D;  av = a + t*128 + 64;  dst = g_U + t*64 + d;
        } else {                         // M1 rows
            int r = idx - 192; int v = r >> 6, d = r & 63; int s = v/3, t = v - s*3;
            row = W + (s*D + d)*D;  av = a + t*128;        dst = g_U + (3 + v)*64 + d;
        }
        *dst = dot64(row, av);
    }
}

// ================= main: 128 threads, 1 batch/warp, B/4 blocks =================
__global__ __launch_bounds__(128, 5) void hetgat_main(
    const float* __restrict__ h,      // (B, 22, 64)
    const void*  __restrict__ maskp,  // (3, B, 22)
    const float* __restrict__ W,      // (3, 64, 64): row k=t*64+d, h contiguous
    float* __restrict__ out,          // (B, 64)
    int B)
{
    __shared__ __align__(16) float s_c[4][96];        // per-warp coeffs c[t*32+node]
    __shared__ __align__(16) float s_g[4][200];       // per-batch g[k], pitch 200
    __shared__ __align__(16) float s_part[4][4][64];  // [kwarp][batch][hcol] partials

    const int tid  = threadIdx.x;
    const int wid  = tid >> 5;
    const int lane = tid & 31;

    const bool u8m = (__ldg(&g_mflag) != 0);
    const int* mi32 = (const int*)maskp;
    const uint8_t* mu8 = (const uint8_t*)maskp;
    const size_t mT = (size_t)B * NN;

    const int b = blockIdx.x * 4 + wid;   // one batch per warp

    // per-lane pair mapping
    const int  tA = lane / 10;                  // 3 for lanes 30,31
    const int  nA = 1 + (lane - tA*10);
    const bool validA = (lane < 30);
    const int  tO = lane / 11;                  // lane oi -> opp pair (tO, nO); slot 31 = (2,20)
    const int  nO = 11 + (lane - tO*11);

    if (b < B) {
        const size_t boff = (size_t)b * NN;
        auto mld = [&](int t, int node) -> int {
            size_t i = (size_t)t * mT + boff + node;
            return u8m ? (int)mu8[i] : mi32[i];
        };
        // mask prefetch (overlaps with h loads)
        int mAv = 1, mOv, mEv = 1, mSv = 0;
        if (validA)     mAv = mld(tA, nA);
        mOv = mld(tO, nO);
        if (lane == 30) mEv = mld(2, 21);
        if (lane < 3)   mSv = mld(lane, 0);

        // ---- hoist h ONCE: lane owns d = 2l, 2l+1; full MLP burst, reused by all passes ----
        const float2* hb2 = (const float2*)(h + (size_t)b * (NN*D));
        float hx[NN], hy[NN];
        #pragma unroll
        for (int n = 0; n < NN; ++n) {
            float2 v = __ldg(hb2 + n*32 + lane);
            hx[n] = v.x; hy[n] = v.y;
        }

        // hoisted w2 lane slices
        float w2x[3], w2y[3];
        #pragma unroll
        for (int t = 0; t < 3; ++t) {
            float2 v = __ldg(((const float2*)(g_U + t*64)) + lane);
            w2x[t] = v.x; w2y[t] = v.y;
        }

        // ======== PASS 1: ally dots (30) + opp pair (2,21) in slot 30 ========
        float p[32];
        #pragma unroll
        for (int n = 1; n <= 10; ++n) {
            p[n-1]      = fmaf(hy[n], w2y[0], hx[n] * w2x[0]);
            p[10 + n-1] = fmaf(hy[n], w2y[1], hx[n] * w2x[1]);
            p[20 + n-1] = fmaf(hy[n], w2y[2], hx[n] * w2x[2]);
        }
        p[30] = fmaf(hy[21], w2y[2], hx[21] * w2x[2]);
        p[31] = 0.f;
        #pragma unroll
        for (int sh = 16; sh >= 1; sh >>= 1) {
            bool up = (lane & sh) != 0;
            #pragma unroll
            for (int k = 0; k < sh; ++k) {
                float send = up ? p[k] : p[k + sh];
                float recv = __shfl_xor_sync(FULLMASK, send, sh);
                float keep = up ? p[k + sh] : p[k];
                p[k] = keep + recv;
            }
        }
        const float dA = p[0];   // lane v: ally dot v (lane30: opp(2,21)); lane31: 0

        // ======== PASS 2: opp dots, slot oi = t*11+(n-11) ========
        // t=0: slots 0..10; t=1: slots 11..21; t=2: slots 22..31 (n=11..20).
        // Pair (2,21) lives in pass-1 slot 30; slot 31 here = (2,20).
        #pragma unroll
        for (int n = 11; n <= 21; ++n) {
            p[n-11]      = fmaf(hy[n], w2y[0], hx[n] * w2x[0]);
            p[11 + n-11] = fmaf(hy[n], w2y[1], hx[n] * w2x[1]);
            if (n < 21) p[22 + n-11] = fmaf(hy[n], w2y[2], hx[n] * w2x[2]);
        }
        #pragma unroll
        for (int sh = 16; sh >= 1; sh >>= 1) {
            bool up = (lane & sh) != 0;
            #pragma unroll
            for (int k = 0; k < sh; ++k) {
                float send = up ? p[k] : p[k + sh];
                float recv = __shfl_xor_sync(FULLMASK, send, sh);
                float keep = up ? p[k + sh] : p[k];
                p[k] = keep + recv;
            }
        }
        const float dO = p[0];   // lane oi: opp dot (tO, nO); lane31 = (2,20)

        // ======== PASS 3: self dots st[s*3+t] (9 values, 16-slot butterfly in p) ========
        #pragma unroll
        for (int v = 0; v < 9; ++v) {
            float2 m = __ldg(((const float2*)(g_U + (3 + v)*64)) + lane);
            p[v] = fmaf(hy[0], m.y, hx[0] * m.x);
        }
        #pragma unroll
        for (int v = 9; v < 16; ++v) p[v] = 0.f;
        #pragma unroll
        for (int sh = 8; sh >= 1; sh >>= 1) {
            bool up = (lane & sh) != 0;
            #pragma unroll
            for (int k = 0; k < sh; ++k) {
                float send = up ? p[k] : p[k + sh];
                float recv = __shfl_xor_sync(FULLMASK, send, sh);
                float keep = up ? p[k + sh] : p[k];
                p[k] = keep + recv;
            }
        }
        p[0] += __shfl_xor_sync(FULLMASK, p[0], 16);
        const float dS = p[0];   // lanes 0-8 hold st[s*3+t]

        // ======== softmax (no max-subtraction; logits small, shift-invariant) ========
        const int tAe = validA ? tA : 2;   // lanes 30,31 borrow t=2 (extra-pair path)
        float s0A = __shfl_sync(FULLMASK, dS, tAe);
        float s1A = __shfl_sync(FULLMASK, dS, 3 + tAe);
        float s2A = __shfl_sync(FULLMASK, dS, 6 + tAe);
        float s0O = __shfl_sync(FULLMASK, dS, tO);
        float s1O = __shfl_sync(FULLMASK, dS, 3 + tO);
        float s2O = __shfl_sync(FULLMASK, dS, 6 + tO);

        float lsA = 0.f;
        if (validA && mAv == 0)
            lsA = __expf(s0A + dA) + __expf(s1A + dA) + __expf(s2A + dA);
        float lsO = 0.f;
        if (mOv == 0)
            lsO = __expf(s0O + dO) + __expf(s1O + dO) + __expf(s2O + dO);
        float lsE = 0.f;
        if (lane == 30 && mEv == 0)      // extra opp pair (t=2, node 21); dot is in dA slot 30
            lsE = __expf(s0O + dA) + __expf(s1O + dA) + __expf(s2O + dA);

        float SA = lsA, SO = lsO + lsE;
        #pragma unroll
        for (int off = 16; off > 0; off >>= 1) {
            SA += __shfl_xor_sync(FULLMASK, SA, off);
            SO += __shfl_xor_sync(FULLMASK, SO, off);
        }

        if (validA)     s_c[wid][tA*32 + nA]  = (mAv == 0) ? __fdividef(lsA, SA) : 0.f;
        s_c[wid][tO*32 + nO] = (mOv == 0) ? __fdividef(lsO, SO) : 0.f;
        if (lane == 30) s_c[wid][2*32 + 21]   = (mEv == 0) ? __fdividef(lsE, SO) : 0.f;
        if (lane < 3)   s_c[wid][lane*32 + 0] = mSv ? 1.0f : 0.0f;
        __syncwarp();

        // ======== combine: g[t][d] = sum_n c[t][n]*h[n][d] (h from registers) ========
        const float* sc = s_c[wid];
        float gx0=0.f, gy0=0.f, gx1=0.f, gy1=0.f, gx2=0.f, gy2=0.f;
        #pragma unroll
        for (int n = 0; n < NN; ++n) {
            float c0 = sc[n], c1 = sc[32 + n], c2 = sc[64 + n];
            gx0 = fmaf(c0, hx[n], gx0); gy0 = fmaf(c0, hy[n], gy0);
            gx1 = fmaf(c1, hx[n], gx1); gy1 = fmaf(c1, hy[n], gy1);
            gx2 = fmaf(c2, hx[n], gx2); gy2 = fmaf(c2, hy[n], gy2);
        }
        ((float2*)(s_g[wid]      ))[lane] = make_float2(gx0, gy0);
        ((float2*)(s_g[wid] +  64))[lane] = make_float2(gx1, gy1);
        ((float2*)(s_g[wid] + 128))[lane] = make_float2(gx2, gy2);
    }
    __syncthreads();

    // ---- block-cooperative mat-vec: warp wid covers k in [48*wid, 48*wid+48) for ALL 4 batches ----
    // lane = (bt, hlg): bt = lane>>3 (batch), hlg = lane&7 (h cols 8*hlg .. 8*hlg+7)
    {
        const int bt  = lane >> 3;
        const int hlg = lane & 7;
        const int kbase = wid * 48;
        const float* gv = s_g[bt];
        ull a0 = 0ull, a1 = 0ull, a2 = 0ull, a3 = 0ull;
        #pragma unroll 8
        for (int i = 0; i < 48; ++i) {
            const int k = kbase + i;
            ull gk = pack2(gv[k]);                       // LDS broadcast per bt
            const ulonglong2* wp = (const ulonglong2*)(W + k*D + hlg*8);
            ulonglong2 w01 = __ldg(wp);
            ulonglong2 w23 = __ldg(wp + 1);
            a0 = fma2(gk, w01.x, a0); a1 = fma2(gk, w01.y, a1);
            a2 = fma2(gk, w23.x, a2); a3 = fma2(gk, w23.y, a3);
        }
        float4 f0 = make_float4(lo32(a0), hi32(a0), lo32(a1), hi32(a1));
        float4 f1 = make_float4(lo32(a2), hi32(a2), lo32(a3), hi32(a3));
        *(float4*)&s_part[wid][bt][hlg*8]     = f0;
        *(float4*)&s_part[wid][bt][hlg*8 + 4] = f1;
    }
    __syncthreads();

    // ---- reduce partials + ELU + store: warp wid writes batch wid, lane owns cols 2l, 2l+1 ----
    if (b < B) {
        float rx = 0.f, ry = 0.f;
        #pragma unroll
        for (int w = 0; w < 4; ++w) {
            float2 v = *(const float2*)&s_part[w][wid][lane*2];
            rx += v.x; ry += v.y;
        }
        float2 o;
        o.x = (rx > 0.f) ? rx : expm1f(rx);
        o.y = (ry > 0.f) ? ry : expm1f(ry);
        ((float2*)(out + (size_t)b * D))[lane] = o;
    }
}

extern "C" void kernel_launch(void* const* d_in, const int* in_sizes, int n_in,
                              void* d_out, int out_size)
{
    const float* h = nullptr;
    const void* mask = nullptr;
    const float* W = nullptr;
    const float* a = nullptr;
    long hsz = 0; int hidx = -1;
    for (int i = 0; i < n_in; ++i) {
        if (in_sizes[i] == 12288)      W = (const float*)d_in[i];
        else if (in_sizes[i] == 384)   a = (const float*)d_in[i];
        if ((long)in_sizes[i] > hsz) { hsz = in_sizes[i]; hidx = i; }
    }
    h = (const float*)d_in[hidx];
    const int B = (int)(hsz / (NN * D));
    for (int i = 0; i < n_in; ++i) {
        if (i != hidx && (long)in_sizes[i] == (long)3 * B * NN)
            mask = d_in[i];
    }

    hetgat_prep<<<6, 128>>>(W, a, mask);
    hetgat_main<<<(B + 3) / 4, 128>>>(h, mask, W, (float*)d_out, B);
}